// round 10
// baseline (speedup 1.0000x reference)
#include <cuda_runtime.h>

typedef unsigned long long ull;

#define OUT_KNN   2097152u
#define OUT_LOCAL 35651584u

__device__ int   g_idx[8 * 2048 * 16];
__device__ float g_h[16384 * 128];
__device__ float g_z[16384 * 128];
__device__ float g_w1t[64 * 128];     // [c][o]
__device__ float g_w2t[128 * 128];    // [c][o]

// Distance matching the reference lowering (proven exact in R7):
//   sq  = (x*x + y*y) + z*z
//   dot = fma(z,z', fma(y,y', x*x'))
//   d2  = (sq_i + sq_j) - 2*dot
__device__ __forceinline__ float d2_of(float4 a, float4 b) {
    float dot = __fmaf_rn(a.z, b.z, __fmaf_rn(a.y, b.y, __fmul_rn(a.x, b.x)));
    return __fsub_rn(__fadd_rn(a.w, b.w), __fmul_rn(2.0f, dot));
}

__device__ __forceinline__ ull fma2(ull a, ull b, ull c) {
    ull d;
    asm("fma.rn.f32x2 %0,%1,%2,%3;" : "=l"(d) : "l"(a), "l"(b), "l"(c));
    return d;
}
__device__ __forceinline__ ull dupf(float a) {
    ull r;
    asm("mov.b64 %0,{%1,%1};" : "=l"(r) : "f"(a));
    return r;
}

// ---------------------------------------------------------------------------
// K0: one-time weight transposes into [c][o] layout.
// ---------------------------------------------------------------------------
__global__ __launch_bounds__(256) void transpose_kernel(const float* __restrict__ w1,
                                                        const float* __restrict__ w2)
{
    int e = blockIdx.x * 256 + threadIdx.x;          // grid covers 16384
    if (e < 8192) {
        int o = e >> 6, c = e & 63;
        g_w1t[c * 128 + o] = w1[e];
    }
    int o2 = e >> 7, c2 = e & 127;
    g_w2t[c2 * 128 + o2] = w2[e];
}

// ---------------------------------------------------------------------------
// K1: exact top-16 KNN, split-j 4 ways (quarter = 512 j's per thread).
//   Pass A: T = max of 16 chunk-minima (chunk=32)  >= 16th smallest (branch-free)
//   Pass B: branch-free candidate log (d2 <= T), flush-and-tighten at 120
//   Pass C: warp-uniform replay with lexicographic (d2, j) insert
//   4-way merge through smem; writes g_idx + local_coords.
// ---------------------------------------------------------------------------
__global__ __launch_bounds__(256) void knn_kernel(const float* __restrict__ coords,
                                                  float* __restrict__ out)
{
    __shared__ float4 cs[2048];
    __shared__ float  md[4][64][16];
    __shared__ int    mi[4][64][16];

    const int t = threadIdx.x, q = t & 63, h = t >> 6;
    const int b = blockIdx.y;
    const int i = blockIdx.x * 64 + q;
    const float* cb = coords + (size_t)b * 3 * 2048;

    for (int j = t; j < 2048; j += 256) {
        float X = cb[j], Y = cb[2048 + j], Z = cb[4096 + j];
        float s = __fadd_rn(__fadd_rn(__fmul_rn(X, X), __fmul_rn(Y, Y)), __fmul_rn(Z, Z));
        cs[j] = make_float4(X, Y, Z, s);
    }
    __syncthreads();

    const float4 ci = cs[i];
    const float INF = __int_as_float(0x7f800000);
    const int jbeg = h << 9;                          // 512 per quarter

    // Pass A: threshold (broadcast LDS, 4 independent min chains)
    float T = -INF;
    for (int ch = 0; ch < 16; ch++) {
        const float4* p = cs + jbeg + ch * 32;
        float m0 = INF, m1 = INF, m2 = INF, m3 = INF;
#pragma unroll
        for (int u = 0; u < 32; u += 4) {
            m0 = fminf(m0, d2_of(ci, p[u]));
            m1 = fminf(m1, d2_of(ci, p[u + 1]));
            m2 = fminf(m2, d2_of(ci, p[u + 2]));
            m3 = fminf(m3, d2_of(ci, p[u + 3]));
        }
        T = fmaxf(T, fminf(fminf(m0, m1), fminf(m2, m3)));
    }

    float dd[16]; int nb[16];
#pragma unroll
    for (int s = 0; s < 16; s++) { dd[s] = INF; nb[s] = 0x7fffffff; }

    auto ins = [&](int j) {
        float de = d2_of(ci, cs[j]);
        if (de < dd[15] || (de == dd[15] && j < nb[15])) {
            float cd = de; int cj = j;
#pragma unroll
            for (int s = 0; s < 16; s++) {
                bool lt = (cd < dd[s]) || (cd == dd[s] && cj < nb[s]);
                float nd = lt ? cd : dd[s];
                int   ni = lt ? cj : nb[s];
                cd = lt ? dd[s] : cd; cj = lt ? nb[s] : cj;
                dd[s] = nd; nb[s] = ni;
            }
        }
    };

    // Pass B: branch-free log; flush-and-tighten is correctness-preserving.
    unsigned short buf[128];
    int cnt = 0;
#pragma unroll 4
    for (int u = 0; u < 512; u++) {
        int j = jbeg + u;
        float d2 = d2_of(ci, cs[j]);
        buf[cnt & 127] = (unsigned short)j;
        cnt += (d2 <= T) ? 1 : 0;
        if (cnt == 120) {
            for (int e = 0; e < 120; e++) ins((int)buf[e]);
            cnt = 0;
            T = fminf(T, dd[15]);
        }
    }
    // Pass C: warp-uniform loop bound, per-lane predicated insert.
    int cm = cnt;
#pragma unroll
    for (int off = 16; off; off >>= 1)
        cm = max(cm, __shfl_xor_sync(0xffffffffu, cm, off));
    for (int e = 0; e < cm; e++)
        if (e < cnt) ins((int)buf[e]);

#pragma unroll
    for (int s = 0; s < 16; s++) { md[h][q][s] = dd[s]; mi[h][q][s] = nb[s]; }
    __syncthreads();
    if (h) return;

    // 4-way tournament merge; quarters are j-ordered, lexicographic compare
    // keeps jax.lax.top_k tie stability exact.
    int ix[4] = {0, 0, 0, 0};
    int fi[16];
#pragma unroll
    for (int s = 0; s < 16; s++) {
        float d0 = md[0][q][ix[0]], d1 = md[1][q][ix[1]];
        float d2v = md[2][q][ix[2]], d3 = md[3][q][ix[3]];
        int j0 = mi[0][q][ix[0]], j1 = mi[1][q][ix[1]];
        int j2 = mi[2][q][ix[2]], j3 = mi[3][q][ix[3]];
        bool a01 = (d0 < d1) || (d0 == d1 && j0 < j1);
        float da = a01 ? d0 : d1; int ja = a01 ? j0 : j1; int ka = a01 ? 0 : 1;
        bool a23 = (d2v < d3) || (d2v == d3 && j2 < j3);
        float db = a23 ? d2v : d3; int jb = a23 ? j2 : j3; int kb = a23 ? 2 : 3;
        bool ab = (da < db) || (da == db && ja < jb);
        fi[s] = ab ? ja : jb;
        ix[ab ? ka : kb]++;
    }

    int* ip = &g_idx[(size_t)(b * 2048 + i) * 16];
#pragma unroll
    for (int s = 0; s < 16; s++) ip[s] = fi[s];

#pragma unroll
    for (int d = 0; d < 3; d++) {
        float cv = d == 0 ? ci.x : (d == 1 ? ci.y : ci.z);
        float* L = out + OUT_LOCAL + ((size_t)(b * 3 + d) * 2048 + i) * 16;
#pragma unroll
        for (int s = 0; s < 16; s++) {
            float4 cn = cs[fi[s]];
            float nv = d == 0 ? cn.x : (d == 1 ? cn.y : cn.z);
            L[s] = __fsub_rn(cv, nv);
        }
    }
}

// ---------------------------------------------------------------------------
// K2a/K2b: per-point MLP. Block = 256 thr = 64 points x 64 output channels
// (channel half selected by blockIdx.x & 1). lane -> 2 channels, warp -> 8
// points. Weight float2 prefetched one c ahead; 8 independent f32x2 accs.
// ---------------------------------------------------------------------------
__global__ __launch_bounds__(256) void layer1_kernel(const float* __restrict__ x,
                                                     const float* __restrict__ g1,
                                                     const float* __restrict__ b1,
                                                     const float* __restrict__ m1,
                                                     const float* __restrict__ v1)
{
    __shared__ float xs[64 * 66];            // [c][p], stride 66
    const int t = threadIdx.x, l = t & 31, wg = t >> 5;
    const int pblk = blockIdx.x >> 1, half = blockIdx.x & 1;
    const int P0 = pblk * 64;
    const int b = P0 >> 11, p0 = P0 & 2047;
    const float* xb = x + (size_t)b * 64 * 2048 + p0;

    for (int e = t; e < 4096; e += 256) {
        int c = e >> 6, p = e & 63;
        xs[c * 66 + p] = xb[c * 2048 + p];
    }
    const int o0 = half * 64 + l * 2;
    float iv0 = g1[o0] / sqrtf(v1[o0] + 1e-5f);
    float cc0 = b1[o0] - m1[o0] * iv0;
    float iv1 = g1[o0 + 1] / sqrtf(v1[o0 + 1] + 1e-5f);
    float cc1 = b1[o0 + 1] - m1[o0 + 1] * iv1;
    __syncthreads();

    ull acc[8];
#pragma unroll
    for (int s = 0; s < 8; s++) acc[s] = 0;

    const float* wbase = g_w1t + o0;
    float2 wv = *(const float2*)(wbase);
#pragma unroll 4
    for (int c = 0; c < 64; c++) {
        float2 wc = wv;
        if (c < 63) wv = *(const float2*)(wbase + (c + 1) * 128);
        ull w0 = dupf(wc.x), w1d = dupf(wc.y);
        const ull* xp = (const ull*)(xs + c * 66 + wg * 8);
        ull x0 = xp[0], x1 = xp[1], x2 = xp[2], x3 = xp[3];
        acc[0] = fma2(w0, x0, acc[0]);  acc[1] = fma2(w0, x1, acc[1]);
        acc[2] = fma2(w0, x2, acc[2]);  acc[3] = fma2(w0, x3, acc[3]);
        acc[4] = fma2(w1d, x0, acc[4]); acc[5] = fma2(w1d, x1, acc[5]);
        acc[6] = fma2(w1d, x2, acc[6]); acc[7] = fma2(w1d, x3, acc[7]);
    }

    float* zb = g_h + ((size_t)P0 + wg * 8) * 128 + o0;
#pragma unroll
    for (int pp = 0; pp < 4; pp++) {
        float s0 = __uint_as_float((unsigned)acc[pp]);
        float s1 = __uint_as_float((unsigned)acc[4 + pp]);
        float2 v0 = make_float2(fmaxf(s0 * iv0 + cc0, 0.f), fmaxf(s1 * iv1 + cc1, 0.f));
        float t0 = __uint_as_float((unsigned)(acc[pp] >> 32));
        float t1 = __uint_as_float((unsigned)(acc[4 + pp] >> 32));
        float2 v1v = make_float2(fmaxf(t0 * iv0 + cc0, 0.f), fmaxf(t1 * iv1 + cc1, 0.f));
        *(float2*)(zb + (size_t)(2 * pp) * 128)     = v0;
        *(float2*)(zb + (size_t)(2 * pp + 1) * 128) = v1v;
    }
}

__global__ __launch_bounds__(256) void layer2_kernel(const float* __restrict__ g2,
                                                     const float* __restrict__ b2,
                                                     const float* __restrict__ m2,
                                                     const float* __restrict__ v2)
{
    __shared__ float xs[128 * 66];           // [c][p], stride 66
    const int t = threadIdx.x, l = t & 31, wg = t >> 5;
    const int pblk = blockIdx.x >> 1, half = blockIdx.x & 1;
    const int P0 = pblk * 64;
    const float* hb = g_h + (size_t)P0 * 128;

    for (int e = t; e < 8192; e += 256) {
        int p = e >> 7, c = e & 127;
        xs[c * 66 + p] = hb[e];
    }
    const int o0 = half * 64 + l * 2;
    float iv0 = g2[o0] / sqrtf(v2[o0] + 1e-5f);
    float cc0 = b2[o0] - m2[o0] * iv0;
    float iv1 = g2[o0 + 1] / sqrtf(v2[o0 + 1] + 1e-5f);
    float cc1 = b2[o0 + 1] - m2[o0 + 1] * iv1;
    __syncthreads();

    ull acc[8];
#pragma unroll
    for (int s = 0; s < 8; s++) acc[s] = 0;

    const float* wbase = g_w2t + o0;
    float2 wv = *(const float2*)(wbase);
#pragma unroll 4
    for (int c = 0; c < 128; c++) {
        float2 wc = wv;
        if (c < 127) wv = *(const float2*)(wbase + (c + 1) * 128);
        ull w0 = dupf(wc.x), w1d = dupf(wc.y);
        const ull* xp = (const ull*)(xs + c * 66 + wg * 8);
        ull x0 = xp[0], x1 = xp[1], x2 = xp[2], x3 = xp[3];
        acc[0] = fma2(w0, x0, acc[0]);  acc[1] = fma2(w0, x1, acc[1]);
        acc[2] = fma2(w0, x2, acc[2]);  acc[3] = fma2(w0, x3, acc[3]);
        acc[4] = fma2(w1d, x0, acc[4]); acc[5] = fma2(w1d, x1, acc[5]);
        acc[6] = fma2(w1d, x2, acc[6]); acc[7] = fma2(w1d, x3, acc[7]);
    }

    float* zb = g_z + ((size_t)P0 + wg * 8) * 128 + o0;
#pragma unroll
    for (int pp = 0; pp < 4; pp++) {
        float s0 = __uint_as_float((unsigned)acc[pp]);
        float s1 = __uint_as_float((unsigned)acc[4 + pp]);
        float2 v0 = make_float2(fmaxf(s0 * iv0 + cc0, 0.f), fmaxf(s1 * iv1 + cc1, 0.f));
        float t0 = __uint_as_float((unsigned)(acc[pp] >> 32));
        float t1 = __uint_as_float((unsigned)(acc[4 + pp] >> 32));
        float2 v1v = make_float2(fmaxf(t0 * iv0 + cc0, 0.f), fmaxf(t1 * iv1 + cc1, 0.f));
        *(float2*)(zb + (size_t)(2 * pp) * 128)     = v0;
        *(float2*)(zb + (size_t)(2 * pp + 1) * 128) = v1v;
    }
}

// ---------------------------------------------------------------------------
// K3: gather. Warp = 2 queries; 4 channel-chunks of 32 through smem;
// y via REDUX.UMAX (z >= +0 post-ReLU => fp max == uint max).
// ---------------------------------------------------------------------------
__global__ __launch_bounds__(128) void gather_kernel(float* __restrict__ out)
{
    __shared__ float S[4][32 * 33];
    const int t = threadIdx.x, w = t >> 5, l = t & 31;
    const int Q0 = blockIdx.x * 8 + w * 2;
    const int qg = Q0 + (l >> 4);
    const int b = qg >> 11, i = qg & 2047, k = l & 15;
    const int i0 = Q0 & 2047;

    const int jl = g_idx[qg * 16 + k];
    const int gr = (b << 11) + jl;
    float* Sw = S[w];
    const unsigned gmask = (l < 16) ? 0x0000FFFFu : 0xFFFF0000u;

    for (int ch = 0; ch < 4; ch++) {
#pragma unroll 8
        for (int r = 0; r < 32; r++) {
            int row = __shfl_sync(0xffffffffu, gr, r);
            Sw[r * 33 + l] = g_z[(size_t)row * 128 + ch * 32 + l];
        }
        __syncwarp();
        float* ob = out + OUT_KNN + ((size_t)(b * 128 + ch * 32) * 2048 + i0) * 16 + l;
        float* yb = out + (size_t)(b * 128 + ch * 32) * 2048 + i;
#pragma unroll 8
        for (int oo = 0; oo < 32; oo++) {
            float v = Sw[l * 33 + oo];
            unsigned mv = __reduce_max_sync(gmask, __float_as_uint(v));
            ob[(size_t)oo * 32768] = v;
            if (k == 0) yb[oo * 2048] = __uint_as_float(mv);
        }
        __syncwarp();
    }
}

extern "C" void kernel_launch(void* const* d_in, const int* in_sizes, int n_in,
                              void* d_out, int out_size)
{
    const float* x      = (const float*)d_in[0];
    const float* coords = (const float*)d_in[1];
    const float* w1     = (const float*)d_in[2];
    const float* g1     = (const float*)d_in[3];
    const float* b1     = (const float*)d_in[4];
    const float* m1     = (const float*)d_in[5];
    const float* v1     = (const float*)d_in[6];
    const float* w2     = (const float*)d_in[7];
    const float* g2     = (const float*)d_in[8];
    const float* b2     = (const float*)d_in[9];
    const float* m2     = (const float*)d_in[10];
    const float* v2     = (const float*)d_in[11];
    float* out = (float*)d_out;

    transpose_kernel<<<64, 256>>>(w1, w2);
    knn_kernel<<<dim3(32, 8), 256>>>(coords, out);
    layer1_kernel<<<512, 256>>>(x, g1, b1, m1, v1);
    layer2_kernel<<<512, 256>>>(g2, b2, m2, v2);
    gather_kernel<<<2048, 128>>>(out);
}

// round 13
// speedup vs baseline: 1.8107x; 1.8107x over previous
#include <cuda_runtime.h>

typedef unsigned long long ull;

#define OUT_KNN   2097152u
#define OUT_LOCAL 35651584u

__device__ int   g_idx[8 * 2048 * 16];
__device__ float g_h[16384 * 128];
__device__ float g_z[16384 * 128];
__device__ float g_w1t[64 * 128];     // [c][o]
__device__ float g_w2t[128 * 128];    // [c][o]

// Distance matching the reference lowering (proven exact in R7):
//   sq  = (x*x + y*y) + z*z
//   dot = fma(z,z', fma(y,y', x*x'))
//   d2  = (sq_i + sq_j) - 2*dot
__device__ __forceinline__ float d2_of(float4 a, float4 b) {
    float dot = __fmaf_rn(a.z, b.z, __fmaf_rn(a.y, b.y, __fmul_rn(a.x, b.x)));
    return __fsub_rn(__fadd_rn(a.w, b.w), __fmul_rn(2.0f, dot));
}

__device__ __forceinline__ ull fma2(ull a, ull b, ull c) {
    ull d;
    asm("fma.rn.f32x2 %0,%1,%2,%3;" : "=l"(d) : "l"(a), "l"(b), "l"(c));
    return d;
}
__device__ __forceinline__ ull dupf(float a) {
    ull r;
    asm("mov.b64 %0,{%1,%1};" : "=l"(r) : "f"(a));
    return r;
}

// ---------------------------------------------------------------------------
// K0: one-time weight transposes into [c][o] layout.
// ---------------------------------------------------------------------------
__global__ __launch_bounds__(256) void transpose_kernel(const float* __restrict__ w1,
                                                        const float* __restrict__ w2)
{
    int e = blockIdx.x * 256 + threadIdx.x;          // grid covers 16384
    if (e < 8192) {
        int o = e >> 6, c = e & 63;
        g_w1t[c * 128 + o] = w1[e];
    }
    int o2 = e >> 7, c2 = e & 127;
    g_w2t[c2 * 128 + o2] = w2[e];
}

// ---------------------------------------------------------------------------
// K1 v4: exact top-16 KNN, split-j 4 ways (512 j's per thread).
//   Pass A: T = max of 16 chunk-minima (chunk=32) >= exact 16th smallest.
//           (#pragma unroll 1 on chunk loop: one body copy in I$.)
//   Pass B: divergent short-body candidate log into buf[512] -- flushless,
//           so no constant-bound replay loop exists to be unrolled.
//   Pass C: ONE dynamic-bound, unroll-1 replay loop holding the single copy
//           of the 16-slot lexicographic (d2, j) insert network.
//   4-way j-ordered tournament merge; writes g_idx + local_coords.
//   Selection output bit-identical to R8/R10 (same T, same insert order).
// ---------------------------------------------------------------------------
__global__ __launch_bounds__(256) void knn_kernel(const float* __restrict__ coords,
                                                  float* __restrict__ out)
{
    __shared__ float4 cs[2048];
    __shared__ float  md[4][64][16];
    __shared__ int    mi[4][64][16];

    const int t = threadIdx.x, q = t & 63, h = t >> 6;
    const int b = blockIdx.y;
    const int i = blockIdx.x * 64 + q;
    const float* cb = coords + (size_t)b * 3 * 2048;

    for (int j = t; j < 2048; j += 256) {
        float X = cb[j], Y = cb[2048 + j], Z = cb[4096 + j];
        float s = __fadd_rn(__fadd_rn(__fmul_rn(X, X), __fmul_rn(Y, Y)), __fmul_rn(Z, Z));
        cs[j] = make_float4(X, Y, Z, s);
    }
    __syncthreads();

    const float4 ci = cs[i];
    const float INF = __int_as_float(0x7f800000);
    const int jbeg = h << 9;                          // 512 per quarter

    // Pass A: threshold (broadcast LDS, 4 independent min chains)
    float T = -INF;
#pragma unroll 1
    for (int ch = 0; ch < 16; ch++) {
        const float4* p = cs + jbeg + ch * 32;
        float m0 = INF, m1 = INF, m2 = INF, m3 = INF;
#pragma unroll
        for (int u = 0; u < 32; u += 4) {
            m0 = fminf(m0, d2_of(ci, p[u]));
            m1 = fminf(m1, d2_of(ci, p[u + 1]));
            m2 = fminf(m2, d2_of(ci, p[u + 2]));
            m3 = fminf(m3, d2_of(ci, p[u + 3]));
        }
        T = fmaxf(T, fminf(fminf(m0, m1), fminf(m2, m3)));
    }

    // Pass B: flushless candidate log (worst case 512 fits; expected ~54).
    unsigned short buf[512];
    int cnt = 0;
#pragma unroll 4
    for (int u = 0; u < 512; u++) {
        int j = jbeg + u;
        float d2 = d2_of(ci, cs[j]);
        if (d2 <= T) buf[cnt++] = (unsigned short)j;
    }

    // Pass C: single replay loop, dynamic bound, exactly one network copy.
    float dd[16]; int nb[16];
#pragma unroll
    for (int s = 0; s < 16; s++) { dd[s] = INF; nb[s] = 0x7fffffff; }

#pragma unroll 1
    for (int e = 0; e < cnt; e++) {
        int j = (int)buf[e];
        float de = d2_of(ci, cs[j]);
        if (de < dd[15] || (de == dd[15] && j < nb[15])) {
            float cd = de; int cj = j;
#pragma unroll
            for (int s = 0; s < 16; s++) {
                bool lt = (cd < dd[s]) || (cd == dd[s] && cj < nb[s]);
                float nd = lt ? cd : dd[s];
                int   ni = lt ? cj : nb[s];
                cd = lt ? dd[s] : cd; cj = lt ? nb[s] : cj;
                dd[s] = nd; nb[s] = ni;
            }
        }
    }

#pragma unroll
    for (int s = 0; s < 16; s++) { md[h][q][s] = dd[s]; mi[h][q][s] = nb[s]; }
    __syncthreads();
    if (h) return;

    // 4-way tournament merge; quarters are j-ordered, lexicographic compare
    // keeps jax.lax.top_k tie stability exact.
    int ix[4] = {0, 0, 0, 0};
    int fi[16];
#pragma unroll
    for (int s = 0; s < 16; s++) {
        float d0 = md[0][q][ix[0]], d1 = md[1][q][ix[1]];
        float d2v = md[2][q][ix[2]], d3 = md[3][q][ix[3]];
        int j0 = mi[0][q][ix[0]], j1 = mi[1][q][ix[1]];
        int j2 = mi[2][q][ix[2]], j3 = mi[3][q][ix[3]];
        bool a01 = (d0 < d1) || (d0 == d1 && j0 < j1);
        float da = a01 ? d0 : d1; int ja = a01 ? j0 : j1; int ka = a01 ? 0 : 1;
        bool a23 = (d2v < d3) || (d2v == d3 && j2 < j3);
        float db = a23 ? d2v : d3; int jb = a23 ? j2 : j3; int kb = a23 ? 2 : 3;
        bool ab = (da < db) || (da == db && ja < jb);
        fi[s] = ab ? ja : jb;
        ix[ab ? ka : kb]++;
    }

    int* ip = &g_idx[(size_t)(b * 2048 + i) * 16];
#pragma unroll
    for (int s = 0; s < 16; s++) ip[s] = fi[s];

#pragma unroll
    for (int d = 0; d < 3; d++) {
        float cv = d == 0 ? ci.x : (d == 1 ? ci.y : ci.z);
        float* L = out + OUT_LOCAL + ((size_t)(b * 3 + d) * 2048 + i) * 16;
#pragma unroll
        for (int s = 0; s < 16; s++) {
            float4 cn = cs[fi[s]];
            float nv = d == 0 ? cn.x : (d == 1 ? cn.y : cn.z);
            L[s] = __fsub_rn(cv, nv);
        }
    }
}

// ---------------------------------------------------------------------------
// K2a/K2b: per-point MLP. Block = 256 thr = 64 points x 64 output channels
// (channel half selected by blockIdx.x & 1). lane -> 2 channels, warp -> 8
// points. Weight float2 prefetched one c ahead; 8 independent f32x2 accs.
// (Unchanged from R10: measured 26.5us l2, ~13us l1.)
// ---------------------------------------------------------------------------
__global__ __launch_bounds__(256) void layer1_kernel(const float* __restrict__ x,
                                                     const float* __restrict__ g1,
                                                     const float* __restrict__ b1,
                                                     const float* __restrict__ m1,
                                                     const float* __restrict__ v1)
{
    __shared__ float xs[64 * 66];            // [c][p], stride 66
    const int t = threadIdx.x, l = t & 31, wg = t >> 5;
    const int pblk = blockIdx.x >> 1, half = blockIdx.x & 1;
    const int P0 = pblk * 64;
    const int b = P0 >> 11, p0 = P0 & 2047;
    const float* xb = x + (size_t)b * 64 * 2048 + p0;

    for (int e = t; e < 4096; e += 256) {
        int c = e >> 6, p = e & 63;
        xs[c * 66 + p] = xb[c * 2048 + p];
    }
    const int o0 = half * 64 + l * 2;
    float iv0 = g1[o0] / sqrtf(v1[o0] + 1e-5f);
    float cc0 = b1[o0] - m1[o0] * iv0;
    float iv1 = g1[o0 + 1] / sqrtf(v1[o0 + 1] + 1e-5f);
    float cc1 = b1[o0 + 1] - m1[o0 + 1] * iv1;
    __syncthreads();

    ull acc[8];
#pragma unroll
    for (int s = 0; s < 8; s++) acc[s] = 0;

    const float* wbase = g_w1t + o0;
    float2 wv = *(const float2*)(wbase);
#pragma unroll 4
    for (int c = 0; c < 64; c++) {
        float2 wc = wv;
        if (c < 63) wv = *(const float2*)(wbase + (c + 1) * 128);
        ull w0 = dupf(wc.x), w1d = dupf(wc.y);
        const ull* xp = (const ull*)(xs + c * 66 + wg * 8);
        ull x0 = xp[0], x1 = xp[1], x2 = xp[2], x3 = xp[3];
        acc[0] = fma2(w0, x0, acc[0]);  acc[1] = fma2(w0, x1, acc[1]);
        acc[2] = fma2(w0, x2, acc[2]);  acc[3] = fma2(w0, x3, acc[3]);
        acc[4] = fma2(w1d, x0, acc[4]); acc[5] = fma2(w1d, x1, acc[5]);
        acc[6] = fma2(w1d, x2, acc[6]); acc[7] = fma2(w1d, x3, acc[7]);
    }

    float* zb = g_h + ((size_t)P0 + wg * 8) * 128 + o0;
#pragma unroll
    for (int pp = 0; pp < 4; pp++) {
        float s0 = __uint_as_float((unsigned)acc[pp]);
        float s1 = __uint_as_float((unsigned)acc[4 + pp]);
        float2 v0 = make_float2(fmaxf(s0 * iv0 + cc0, 0.f), fmaxf(s1 * iv1 + cc1, 0.f));
        float t0 = __uint_as_float((unsigned)(acc[pp] >> 32));
        float t1 = __uint_as_float((unsigned)(acc[4 + pp] >> 32));
        float2 v1v = make_float2(fmaxf(t0 * iv0 + cc0, 0.f), fmaxf(t1 * iv1 + cc1, 0.f));
        *(float2*)(zb + (size_t)(2 * pp) * 128)     = v0;
        *(float2*)(zb + (size_t)(2 * pp + 1) * 128) = v1v;
    }
}

__global__ __launch_bounds__(256) void layer2_kernel(const float* __restrict__ g2,
                                                     const float* __restrict__ b2,
                                                     const float* __restrict__ m2,
                                                     const float* __restrict__ v2)
{
    __shared__ float xs[128 * 66];           // [c][p], stride 66
    const int t = threadIdx.x, l = t & 31, wg = t >> 5;
    const int pblk = blockIdx.x >> 1, half = blockIdx.x & 1;
    const int P0 = pblk * 64;
    const float* hb = g_h + (size_t)P0 * 128;

    for (int e = t; e < 8192; e += 256) {
        int p = e >> 7, c = e & 127;
        xs[c * 66 + p] = hb[e];
    }
    const int o0 = half * 64 + l * 2;
    float iv0 = g2[o0] / sqrtf(v2[o0] + 1e-5f);
    float cc0 = b2[o0] - m2[o0] * iv0;
    float iv1 = g2[o0 + 1] / sqrtf(v2[o0 + 1] + 1e-5f);
    float cc1 = b2[o0 + 1] - m2[o0 + 1] * iv1;
    __syncthreads();

    ull acc[8];
#pragma unroll
    for (int s = 0; s < 8; s++) acc[s] = 0;

    const float* wbase = g_w2t + o0;
    float2 wv = *(const float2*)(wbase);
#pragma unroll 4
    for (int c = 0; c < 128; c++) {
        float2 wc = wv;
        if (c < 127) wv = *(const float2*)(wbase + (c + 1) * 128);
        ull w0 = dupf(wc.x), w1d = dupf(wc.y);
        const ull* xp = (const ull*)(xs + c * 66 + wg * 8);
        ull x0 = xp[0], x1 = xp[1], x2 = xp[2], x3 = xp[3];
        acc[0] = fma2(w0, x0, acc[0]);  acc[1] = fma2(w0, x1, acc[1]);
        acc[2] = fma2(w0, x2, acc[2]);  acc[3] = fma2(w0, x3, acc[3]);
        acc[4] = fma2(w1d, x0, acc[4]); acc[5] = fma2(w1d, x1, acc[5]);
        acc[6] = fma2(w1d, x2, acc[6]); acc[7] = fma2(w1d, x3, acc[7]);
    }

    float* zb = g_z + ((size_t)P0 + wg * 8) * 128 + o0;
#pragma unroll
    for (int pp = 0; pp < 4; pp++) {
        float s0 = __uint_as_float((unsigned)acc[pp]);
        float s1 = __uint_as_float((unsigned)acc[4 + pp]);
        float2 v0 = make_float2(fmaxf(s0 * iv0 + cc0, 0.f), fmaxf(s1 * iv1 + cc1, 0.f));
        float t0 = __uint_as_float((unsigned)(acc[pp] >> 32));
        float t1 = __uint_as_float((unsigned)(acc[4 + pp] >> 32));
        float2 v1v = make_float2(fmaxf(t0 * iv0 + cc0, 0.f), fmaxf(t1 * iv1 + cc1, 0.f));
        *(float2*)(zb + (size_t)(2 * pp) * 128)     = v0;
        *(float2*)(zb + (size_t)(2 * pp + 1) * 128) = v1v;
    }
}

// ---------------------------------------------------------------------------
// K3: gather. Warp = 2 queries; 4 channel-chunks of 32 through smem;
// y via REDUX.UMAX (z >= +0 post-ReLU => fp max == uint max).
// ---------------------------------------------------------------------------
__global__ __launch_bounds__(128) void gather_kernel(float* __restrict__ out)
{
    __shared__ float S[4][32 * 33];
    const int t = threadIdx.x, w = t >> 5, l = t & 31;
    const int Q0 = blockIdx.x * 8 + w * 2;
    const int qg = Q0 + (l >> 4);
    const int b = qg >> 11, i = qg & 2047, k = l & 15;
    const int i0 = Q0 & 2047;

    const int jl = g_idx[qg * 16 + k];
    const int gr = (b << 11) + jl;
    float* Sw = S[w];
    const unsigned gmask = (l < 16) ? 0x0000FFFFu : 0xFFFF0000u;

    for (int ch = 0; ch < 4; ch++) {
#pragma unroll 8
        for (int r = 0; r < 32; r++) {
            int row = __shfl_sync(0xffffffffu, gr, r);
            Sw[r * 33 + l] = g_z[(size_t)row * 128 + ch * 32 + l];
        }
        __syncwarp();
        float* ob = out + OUT_KNN + ((size_t)(b * 128 + ch * 32) * 2048 + i0) * 16 + l;
        float* yb = out + (size_t)(b * 128 + ch * 32) * 2048 + i;
#pragma unroll 8
        for (int oo = 0; oo < 32; oo++) {
            float v = Sw[l * 33 + oo];
            unsigned mv = __reduce_max_sync(gmask, __float_as_uint(v));
            ob[(size_t)oo * 32768] = v;
            if (k == 0) yb[oo * 2048] = __uint_as_float(mv);
        }
        __syncwarp();
    }
}

extern "C" void kernel_launch(void* const* d_in, const int* in_sizes, int n_in,
                              void* d_out, int out_size)
{
    const float* x      = (const float*)d_in[0];
    const float* coords = (const float*)d_in[1];
    const float* w1     = (const float*)d_in[2];
    const float* g1     = (const float*)d_in[3];
    const float* b1     = (const float*)d_in[4];
    const float* m1     = (const float*)d_in[5];
    const float* v1     = (const float*)d_in[6];
    const float* w2     = (const float*)d_in[7];
    const float* g2     = (const float*)d_in[8];
    const float* b2     = (const float*)d_in[9];
    const float* m2     = (const float*)d_in[10];
    const float* v2     = (const float*)d_in[11];
    float* out = (float*)d_out;

    transpose_kernel<<<64, 256>>>(w1, w2);
    knn_kernel<<<dim3(32, 8), 256>>>(coords, out);
    layer1_kernel<<<512, 256>>>(x, g1, b1, m1, v1);
    layer2_kernel<<<512, 256>>>(g2, b2, m2, v2);
    gather_kernel<<<2048, 128>>>(out);
}